// round 12
// baseline (speedup 1.0000x reference)
#include <cuda_runtime.h>
#include <cuda_fp16.h>
#include <math.h>

#define BB 16
#define SS 1024
#define DD 1024
#define HH 16
#define DH 64

// Device scratch (no allocations allowed).
__device__ float  g_q[BB * HH * SS * DH];   // fp32 head-split Q/K/V
__device__ float  g_k[BB * HH * SS * DH];
__device__ float  g_v[BB * HH * SS * DH];
__device__ __half g_xh[BB * SS * DD];       // fp16 X
__device__ __half g_wh[3 * DD * DD];        // fp16 Wq,Wk,Wv

// ---------------------------------------------------------------------------
__device__ __forceinline__ void mma_f16(float* d, const unsigned* a, const unsigned* b) {
    asm volatile(
        "mma.sync.aligned.m16n8k16.row.col.f32.f16.f16.f32 "
        "{%0,%1,%2,%3},{%4,%5,%6,%7},{%8,%9},{%0,%1,%2,%3};"
        : "+f"(d[0]), "+f"(d[1]), "+f"(d[2]), "+f"(d[3])
        : "r"(a[0]), "r"(a[1]), "r"(a[2]), "r"(a[3]), "r"(b[0]), "r"(b[1]));
}

__device__ __forceinline__ unsigned h2u(__half2 h) {
    return *(unsigned*)&h;
}

// ---------------------------------------------------------------------------
// Pre-pass: fp32 -> fp16 (rn), 8 elements per thread.
// ---------------------------------------------------------------------------
__global__ void to_half(__half* __restrict__ dst, const float* __restrict__ src, int n8)
{
    int i = blockIdx.x * blockDim.x + threadIdx.x;
    if (i < n8) {
        float4 a = ((const float4*)src)[2 * i];
        float4 b = ((const float4*)src)[2 * i + 1];
        uint4 u;
        u.x = h2u(__floats2half2_rn(a.x, a.y));
        u.y = h2u(__floats2half2_rn(a.z, a.w));
        u.z = h2u(__floats2half2_rn(b.x, b.y));
        u.w = h2u(__floats2half2_rn(b.z, b.w));
        ((uint4*)dst)[i] = u;
    }
}

// ---------------------------------------------------------------------------
// QKV projection, fp16 pipelined: Y = X @ W^T + b (fp32 out).
// BM=BN=128, BK=32, 256 thr (8 warps 4x2, warp tile 32x64).
// Double-buffered smem + register prefetch; ONE sync per k-iter:
//   iter t: STS(tile t+1 -> buf^1) ; LDG(tile t+2 -> regs) ; mma(buf) ; sync
// ---------------------------------------------------------------------------
__global__ __launch_bounds__(256)
void qkv_gemm(const float* __restrict__ bias, int which)
{
    __shared__ __half sa[2][128][40];
    __shared__ __half sb[2][128][40];

    float* __restrict__ Y = (which == 0) ? g_q : (which == 1) ? g_k : g_v;
    const __half* __restrict__ Xh = g_xh;
    const __half* __restrict__ Wh = g_wh + (size_t)which * DD * DD;

    const int tid  = threadIdx.x;
    const int lane = tid & 31;
    const int warp = tid >> 5;
    const int wm   = (warp & 3) * 32;
    const int wn   = (warp >> 2) * 64;
    const int m0   = blockIdx.y * 128;
    const int n0   = blockIdx.x * 128;

    // chunk map: thread -> rows (row, row+64), chunk col c (8 halfs = 16B)
    const int row = tid >> 2;       // 0..63
    const int cc  = (tid & 3) * 8;  // 0,8,16,24
    const __half* pa0 = Xh + (size_t)(m0 + row) * DD + cc;
    const __half* pa1 = Xh + (size_t)(m0 + row + 64) * DD + cc;
    const __half* pb0 = Wh + (size_t)(n0 + row) * DD + cc;
    const __half* pb1 = Wh + (size_t)(n0 + row + 64) * DD + cc;

    const int r4 = lane >> 2;
    const int c4 = lane & 3;

    float acc[2][8][4];
    #pragma unroll
    for (int i = 0; i < 2; i++)
        #pragma unroll
        for (int j = 0; j < 8; j++)
            #pragma unroll
            for (int c = 0; c < 4; c++) acc[i][j][c] = 0.0f;

    uint4 ra0, ra1, rb0, rb1;

    // tile 0 -> regs -> buf0
    ra0 = *(const uint4*)(pa0); ra1 = *(const uint4*)(pa1);
    rb0 = *(const uint4*)(pb0); rb1 = *(const uint4*)(pb1);
    *(uint4*)&sa[0][row][cc]      = ra0;
    *(uint4*)&sa[0][row + 64][cc] = ra1;
    *(uint4*)&sb[0][row][cc]      = rb0;
    *(uint4*)&sb[0][row + 64][cc] = rb1;
    // tile 1 -> regs
    ra0 = *(const uint4*)(pa0 + 32); ra1 = *(const uint4*)(pa1 + 32);
    rb0 = *(const uint4*)(pb0 + 32); rb1 = *(const uint4*)(pb1 + 32);
    __syncthreads();

    for (int kt = 0; kt < 32; kt++) {
        const int cur = kt & 1;
        if (kt < 31) {
            // store tile kt+1 into the other buffer (readers of it are done)
            *(uint4*)&sa[cur ^ 1][row][cc]      = ra0;
            *(uint4*)&sa[cur ^ 1][row + 64][cc] = ra1;
            *(uint4*)&sb[cur ^ 1][row][cc]      = rb0;
            *(uint4*)&sb[cur ^ 1][row + 64][cc] = rb1;
            if (kt < 30) {
                const int k0 = (kt + 2) * 32;
                ra0 = *(const uint4*)(pa0 + k0); ra1 = *(const uint4*)(pa1 + k0);
                rb0 = *(const uint4*)(pb0 + k0); rb1 = *(const uint4*)(pb1 + k0);
            }
        }

        #pragma unroll
        for (int ks = 0; ks < 2; ks++) {
            const int kk = ks * 16 + 2 * c4;
            unsigned af[2][4];
            #pragma unroll
            for (int mt = 0; mt < 2; mt++) {
                const int rb = wm + mt * 16;
                af[mt][0] = *(const unsigned*)&sa[cur][rb + r4    ][kk    ];
                af[mt][1] = *(const unsigned*)&sa[cur][rb + r4 + 8][kk    ];
                af[mt][2] = *(const unsigned*)&sa[cur][rb + r4    ][kk + 8];
                af[mt][3] = *(const unsigned*)&sa[cur][rb + r4 + 8][kk + 8];
            }
            #pragma unroll
            for (int nt = 0; nt < 8; nt++) {
                const int cb = wn + nt * 8;
                unsigned bf[2];
                bf[0] = *(const unsigned*)&sb[cur][cb + r4][kk    ];
                bf[1] = *(const unsigned*)&sb[cur][cb + r4][kk + 8];
                mma_f16(acc[0][nt], af[0], bf);
                mma_f16(acc[1][nt], af[1], bf);
            }
        }
        __syncthreads();
    }

    // Epilogue: bias + head-split scatter (fp32).
    #pragma unroll
    for (int mt = 0; mt < 2; mt++) {
        const int mA = m0 + wm + mt * 16 + r4;
        const int mB = mA + 8;
        const int bA = mA >> 10, sA_ = mA & 1023;
        const int bB = mB >> 10, sB_ = mB & 1023;
        #pragma unroll
        for (int nt = 0; nt < 8; nt++) {
            const int col = n0 + wn + nt * 8 + 2 * c4;
            const int h = col >> 6, d = col & 63;
            const float b0 = bias[col], b1 = bias[col + 1];
            float2 vA = make_float2(acc[mt][nt][0] + b0, acc[mt][nt][1] + b1);
            float2 vB = make_float2(acc[mt][nt][2] + b0, acc[mt][nt][3] + b1);
            *(float2*)(Y + (((size_t)(bA * HH + h) * SS + sA_) * DH) + d) = vA;
            *(float2*)(Y + (((size_t)(bB * HH + h) * SS + sB_) * DH) + d) = vB;
        }
    }
}

// ---------------------------------------------------------------------------
// Flash attention, fp16 m16n8k16 mma — byte-identical to R10/R11 (427us).
// ---------------------------------------------------------------------------
__global__ __launch_bounds__(128)
void attn_kernel(float* __restrict__ out)
{
    __shared__ __half sk[32][72];
    __shared__ unsigned sv2[16][72];
    __shared__ __half sp[4][16][72];

    const int tid  = threadIdx.x;
    const int lane = tid & 31;
    const int warp = tid >> 5;
    const int bh   = blockIdx.y;
    const int b    = bh >> 4;
    const int h    = bh & 15;
    const int qrow0 = blockIdx.x * 64 + warp * 16;

    const int r4 = lane >> 2;
    const int c4 = lane & 3;

    const float* Qb = g_q + (size_t)bh * SS * DH;
    const float* Kb = g_k + (size_t)bh * SS * DH;
    const float* Vb = g_v + (size_t)bh * SS * DH;

    {
        #pragma unroll
        for (int i = 0; i < 8; i++) {
            const int idx = lane + i * 32;
            const int row = idx >> 4;
            const int cc  = (idx & 15) * 4;
            float4 t = *(const float4*)(Qb + (size_t)(qrow0 + row) * DH + cc);
            unsigned h0 = h2u(__floats2half2_rn(t.x * 0.125f, t.y * 0.125f));
            unsigned h1 = h2u(__floats2half2_rn(t.z * 0.125f, t.w * 0.125f));
            *(uint2*)&sp[warp][row][cc] = make_uint2(h0, h1);
        }
    }
    __syncwarp();
    unsigned qa[4][4];
    #pragma unroll
    for (int ks = 0; ks < 4; ks++) {
        const int kk = ks * 16 + 2 * c4;
        qa[ks][0] = *(const unsigned*)&sp[warp][r4    ][kk    ];
        qa[ks][1] = *(const unsigned*)&sp[warp][r4 + 8][kk    ];
        qa[ks][2] = *(const unsigned*)&sp[warp][r4    ][kk + 8];
        qa[ks][3] = *(const unsigned*)&sp[warp][r4 + 8][kk + 8];
    }
    __syncwarp();

    float o[8][4];
    #pragma unroll
    for (int nt = 0; nt < 8; nt++)
        #pragma unroll
        for (int c = 0; c < 4; c++) o[nt][c] = 0.0f;
    float m0v = -INFINITY, m1v = -INFINITY;
    float l0 = 0.0f, l1 = 0.0f;

    for (int t0 = 0; t0 < SS; t0 += 32) {
        __syncthreads();
        #pragma unroll
        for (int i = 0; i < 4; i++) {
            const int idx = tid + i * 128;
            const int row = idx >> 4;
            const int cc  = (idx & 15) * 4;
            float4 kt4 = *(const float4*)(Kb + (size_t)(t0 + row) * DH + cc);
            unsigned h0 = h2u(__floats2half2_rn(kt4.x, kt4.y));
            unsigned h1 = h2u(__floats2half2_rn(kt4.z, kt4.w));
            *(uint2*)&sk[row][cc] = make_uint2(h0, h1);
        }
        {
            const int kvp = tid >> 3;
            const int d0  = (tid & 7) * 8;
            const float* v0 = Vb + (size_t)(t0 + 2 * kvp) * DH + d0;
            const float* v1 = v0 + DH;
            float4 a0 = *(const float4*)(v0);
            float4 a1 = *(const float4*)(v0 + 4);
            float4 b0 = *(const float4*)(v1);
            float4 b1 = *(const float4*)(v1 + 4);
            uint4 w0, w1;
            w0.x = h2u(__floats2half2_rn(a0.x, b0.x));
            w0.y = h2u(__floats2half2_rn(a0.y, b0.y));
            w0.z = h2u(__floats2half2_rn(a0.z, b0.z));
            w0.w = h2u(__floats2half2_rn(a0.w, b0.w));
            w1.x = h2u(__floats2half2_rn(a1.x, b1.x));
            w1.y = h2u(__floats2half2_rn(a1.y, b1.y));
            w1.z = h2u(__floats2half2_rn(a1.z, b1.z));
            w1.w = h2u(__floats2half2_rn(a1.w, b1.w));
            *(uint4*)&sv2[kvp][d0]     = w0;
            *(uint4*)&sv2[kvp][d0 + 4] = w1;
        }
        __syncthreads();

        float s[4][4];
        #pragma unroll
        for (int nt = 0; nt < 4; nt++) {
            #pragma unroll
            for (int c = 0; c < 4; c++) s[nt][c] = 0.0f;
            #pragma unroll
            for (int ks = 0; ks < 4; ks++) {
                const int kk = ks * 16 + 2 * c4;
                unsigned bf[2];
                bf[0] = *(const unsigned*)&sk[nt * 8 + r4][kk    ];
                bf[1] = *(const unsigned*)&sk[nt * 8 + r4][kk + 8];
                mma_f16(s[nt], qa[ks], bf);
            }
        }

        float tm0 = -INFINITY, tm1 = -INFINITY;
        #pragma unroll
        for (int nt = 0; nt < 4; nt++) {
            tm0 = fmaxf(tm0, fmaxf(s[nt][0], s[nt][1]));
            tm1 = fmaxf(tm1, fmaxf(s[nt][2], s[nt][3]));
        }
        tm0 = fmaxf(tm0, __shfl_xor_sync(0xffffffffu, tm0, 1));
        tm0 = fmaxf(tm0, __shfl_xor_sync(0xffffffffu, tm0, 2));
        tm1 = fmaxf(tm1, __shfl_xor_sync(0xffffffffu, tm1, 1));
        tm1 = fmaxf(tm1, __shfl_xor_sync(0xffffffffu, tm1, 2));

        const float mn0 = fmaxf(m0v, tm0);
        const float mn1 = fmaxf(m1v, tm1);
        const float sc0 = __expf(m0v - mn0);
        const float sc1 = __expf(m1v - mn1);
        m0v = mn0; m1v = mn1;

        float ps0 = 0.0f, ps1 = 0.0f;
        #pragma unroll
        for (int nt = 0; nt < 4; nt++) {
            s[nt][0] = __expf(s[nt][0] - mn0);
            s[nt][1] = __expf(s[nt][1] - mn0);
            s[nt][2] = __expf(s[nt][2] - mn1);
            s[nt][3] = __expf(s[nt][3] - mn1);
            ps0 += s[nt][0] + s[nt][1];
            ps1 += s[nt][2] + s[nt][3];
        }
        ps0 += __shfl_xor_sync(0xffffffffu, ps0, 1);
        ps0 += __shfl_xor_sync(0xffffffffu, ps0, 2);
        ps1 += __shfl_xor_sync(0xffffffffu, ps1, 1);
        ps1 += __shfl_xor_sync(0xffffffffu, ps1, 2);
        l0 = l0 * sc0 + ps0;
        l1 = l1 * sc1 + ps1;

        #pragma unroll
        for (int nt = 0; nt < 8; nt++) {
            o[nt][0] *= sc0; o[nt][1] *= sc0;
            o[nt][2] *= sc1; o[nt][3] *= sc1;
        }

        #pragma unroll
        for (int nt = 0; nt < 4; nt++) {
            const int pc = nt * 8 + 2 * c4;
            *(unsigned*)&sp[warp][r4    ][pc] = h2u(__floats2half2_rn(s[nt][0], s[nt][1]));
            *(unsigned*)&sp[warp][r4 + 8][pc] = h2u(__floats2half2_rn(s[nt][2], s[nt][3]));
        }
        __syncwarp();

        unsigned pa[2][4];
        #pragma unroll
        for (int ks = 0; ks < 2; ks++) {
            const int kk = ks * 16 + 2 * c4;
            pa[ks][0] = *(const unsigned*)&sp[warp][r4    ][kk    ];
            pa[ks][1] = *(const unsigned*)&sp[warp][r4 + 8][kk    ];
            pa[ks][2] = *(const unsigned*)&sp[warp][r4    ][kk + 8];
            pa[ks][3] = *(const unsigned*)&sp[warp][r4 + 8][kk + 8];
        }

        #pragma unroll
        for (int nt = 0; nt < 8; nt++) {
            #pragma unroll
            for (int ks = 0; ks < 2; ks++) {
                unsigned bf[2];
                bf[0] = sv2[ks * 8 + c4    ][nt * 8 + r4];
                bf[1] = sv2[ks * 8 + c4 + 4][nt * 8 + r4];
                mma_f16(o[nt], pa[ks], bf);
            }
        }
        __syncwarp();
    }

    const float inv0 = 1.0f / l0;
    const float inv1 = 1.0f / l1;
    const int rA = qrow0 + r4;
    const int rB = rA + 8;
    float* oA = out + ((size_t)(b * SS + rA)) * DD + h * DH;
    float* oB = out + ((size_t)(b * SS + rB)) * DD + h * DH;
    #pragma unroll
    for (int nt = 0; nt < 8; nt++) {
        const int d = nt * 8 + 2 * c4;
        *(float2*)(oA + d) = make_float2(o[nt][0] * inv0, o[nt][1] * inv0);
        *(float2*)(oB + d) = make_float2(o[nt][2] * inv1, o[nt][3] * inv1);
    }
}

extern "C" void kernel_launch(void* const* d_in, const int* in_sizes, int n_in,
                              void* d_out, int out_size)
{
    const float* x  = (const float*)d_in[0];
    const float* Wq = (const float*)d_in[1];
    const float* bq = (const float*)d_in[2];
    const float* Wk = (const float*)d_in[3];
    const float* bk = (const float*)d_in[4];
    const float* Wv = (const float*)d_in[5];
    const float* bv = (const float*)d_in[6];
    float* out = (float*)d_out;

    __half* gxh; cudaGetSymbolAddress((void**)&gxh, g_xh);
    __half* gwh; cudaGetSymbolAddress((void**)&gwh, g_wh);

    to_half<<<(BB * SS * DD / 8 + 255) / 256, 256>>>(gxh, x, BB * SS * DD / 8);
    to_half<<<(DD * DD / 8 + 255) / 256, 256>>>(gwh,               Wq, DD * DD / 8);
    to_half<<<(DD * DD / 8 + 255) / 256, 256>>>(gwh + DD * DD,     Wk, DD * DD / 8);
    to_half<<<(DD * DD / 8 + 255) / 256, 256>>>(gwh + 2 * DD * DD, Wv, DD * DD / 8);

    dim3 gg(DD / 128, (BB * SS) / 128);   // (8, 128)
    qkv_gemm<<<gg, 256>>>(bq, 0);
    qkv_gemm<<<gg, 256>>>(bk, 1);
    qkv_gemm<<<gg, 256>>>(bv, 2);

    dim3 ga(SS / 64, BB * HH);            // (16, 256)
    attn_kernel<<<ga, 128>>>(out);
}

// round 13
// speedup vs baseline: 1.6961x; 1.6961x over previous
#include <cuda_runtime.h>
#include <cuda_fp16.h>
#include <math.h>

#define BB 16
#define SS 1024
#define DD 1024
#define HH 16
#define DH 64

// Device scratch (no allocations allowed).
__device__ float  g_q[BB * HH * SS * DH];   // fp32 head-split Q/K/V
__device__ float  g_k[BB * HH * SS * DH];
__device__ float  g_v[BB * HH * SS * DH];
__device__ __half g_xh[BB * SS * DD];       // fp16 X
__device__ __half g_wh[3 * DD * DD];        // fp16 Wq,Wk,Wv

// ---------------------------------------------------------------------------
__device__ __forceinline__ void mma_f16(float* d, const unsigned* a, const unsigned* b) {
    asm volatile(
        "mma.sync.aligned.m16n8k16.row.col.f32.f16.f16.f32 "
        "{%0,%1,%2,%3},{%4,%5,%6,%7},{%8,%9},{%0,%1,%2,%3};"
        : "+f"(d[0]), "+f"(d[1]), "+f"(d[2]), "+f"(d[3])
        : "r"(a[0]), "r"(a[1]), "r"(a[2]), "r"(a[3]), "r"(b[0]), "r"(b[1]));
}

__device__ __forceinline__ unsigned h2u(__half2 h) {
    return *(unsigned*)&h;
}

// ---------------------------------------------------------------------------
// Pre-pass: fp32 -> fp16 (rn), 8 elements per thread.
// ---------------------------------------------------------------------------
__global__ void to_half(__half* __restrict__ dst, const float* __restrict__ src, int n8)
{
    int i = blockIdx.x * blockDim.x + threadIdx.x;
    if (i < n8) {
        float4 a = ((const float4*)src)[2 * i];
        float4 b = ((const float4*)src)[2 * i + 1];
        uint4 u;
        u.x = h2u(__floats2half2_rn(a.x, a.y));
        u.y = h2u(__floats2half2_rn(a.z, a.w));
        u.z = h2u(__floats2half2_rn(b.x, b.y));
        u.w = h2u(__floats2half2_rn(b.z, b.w));
        ((uint4*)dst)[i] = u;
    }
}

// ---------------------------------------------------------------------------
// QKV projection: Y = X @ W^T + b (fp32 out). fp16 m16n8k16 mma.
// EXACT R11 loop cadence (LDG -> sync -> STS -> sync -> mma); only change:
// fp16 source (uint2 loads, no in-loop cvt). BM=BN=128, BK=32, 256 thr.
// ---------------------------------------------------------------------------
__global__ __launch_bounds__(256)
void qkv_gemm(const float* __restrict__ bias, int which)
{
    __shared__ __half sa[128][40];   // [m][k]
    __shared__ __half sb[128][40];   // [n][k]

    float* __restrict__ Y = (which == 0) ? g_q : (which == 1) ? g_k : g_v;
    const __half* __restrict__ Xh = g_xh;
    const __half* __restrict__ Wh = g_wh + (size_t)which * DD * DD;

    const int tid  = threadIdx.x;
    const int lane = tid & 31;
    const int warp = tid >> 5;
    const int wm   = (warp & 3) * 32;
    const int wn   = (warp >> 2) * 64;
    const int m0   = blockIdx.y * 128;
    const int n0   = blockIdx.x * 128;

    // coalesced map (R11): 8 threads per row (64B contiguous), 4 rows spaced 32
    const int lr = tid >> 3;        // 0..31
    const int lc = (tid & 7) * 4;   // half cols 0,4,...,28

    const int r4 = lane >> 2;
    const int c4 = lane & 3;

    float acc[2][8][4];
    #pragma unroll
    for (int i = 0; i < 2; i++)
        #pragma unroll
        for (int j = 0; j < 8; j++)
            #pragma unroll
            for (int c = 0; c < 4; c++) acc[i][j][c] = 0.0f;

    for (int k0 = 0; k0 < DD; k0 += 32) {
        uint2 ua[4], ub[4];
        #pragma unroll
        for (int i = 0; i < 4; i++) {
            ua[i] = *(const uint2*)(Xh + (size_t)(m0 + lr + 32 * i) * DD + k0 + lc);
            ub[i] = *(const uint2*)(Wh + (size_t)(n0 + lr + 32 * i) * DD + k0 + lc);
        }
        __syncthreads();   // previous iteration's mma done reading smem
        #pragma unroll
        for (int i = 0; i < 4; i++) {
            *(uint2*)&sa[lr + 32 * i][lc] = ua[i];
            *(uint2*)&sb[lr + 32 * i][lc] = ub[i];
        }
        __syncthreads();

        #pragma unroll
        for (int ks = 0; ks < 2; ks++) {          // 2 x k16 per BK=32
            const int kk = ks * 16 + 2 * c4;
            unsigned af[2][4];
            #pragma unroll
            for (int mt = 0; mt < 2; mt++) {
                const int rb = wm + mt * 16;
                af[mt][0] = *(const unsigned*)&sa[rb + r4    ][kk    ];
                af[mt][1] = *(const unsigned*)&sa[rb + r4 + 8][kk    ];
                af[mt][2] = *(const unsigned*)&sa[rb + r4    ][kk + 8];
                af[mt][3] = *(const unsigned*)&sa[rb + r4 + 8][kk + 8];
            }
            #pragma unroll
            for (int nt = 0; nt < 8; nt++) {
                const int cb = wn + nt * 8;
                unsigned bf[2];
                bf[0] = *(const unsigned*)&sb[cb + r4][kk    ];
                bf[1] = *(const unsigned*)&sb[cb + r4][kk + 8];
                mma_f16(acc[0][nt], af[0], bf);
                mma_f16(acc[1][nt], af[1], bf);
            }
        }
    }

    // Epilogue: bias + head-split scatter (fp32).
    #pragma unroll
    for (int mt = 0; mt < 2; mt++) {
        const int mA = m0 + wm + mt * 16 + r4;
        const int mB = mA + 8;
        const int bA = mA >> 10, sA_ = mA & 1023;
        const int bB = mB >> 10, sB_ = mB & 1023;
        #pragma unroll
        for (int nt = 0; nt < 8; nt++) {
            const int col = n0 + wn + nt * 8 + 2 * c4;
            const int h = col >> 6, d = col & 63;
            const float b0 = bias[col], b1 = bias[col + 1];
            float2 vA = make_float2(acc[mt][nt][0] + b0, acc[mt][nt][1] + b1);
            float2 vB = make_float2(acc[mt][nt][2] + b0, acc[mt][nt][3] + b1);
            *(float2*)(Y + (((size_t)(bA * HH + h) * SS + sA_) * DH) + d) = vA;
            *(float2*)(Y + (((size_t)(bB * HH + h) * SS + sB_) * DH) + d) = vB;
        }
    }
}

// ---------------------------------------------------------------------------
// Flash attention, fp16 m16n8k16 mma. R10/R11 structure with BC=64:
// half the tile iterations -> half the syncs / softmax passes / O rescales.
// Block = 128 thr (4 warps), 16 q-rows per warp, Dh=64.
// ---------------------------------------------------------------------------
__global__ __launch_bounds__(128)
void attn_kernel(float* __restrict__ out)
{
    __shared__ __half sk[64][72];
    __shared__ unsigned sv2[32][72];
    __shared__ __half sp[4][16][72];

    const int tid  = threadIdx.x;
    const int lane = tid & 31;
    const int warp = tid >> 5;
    const int bh   = blockIdx.y;
    const int b    = bh >> 4;
    const int h    = bh & 15;
    const int qrow0 = blockIdx.x * 64 + warp * 16;

    const int r4 = lane >> 2;
    const int c4 = lane & 3;

    const float* Qb = g_q + (size_t)bh * SS * DH;
    const float* Kb = g_k + (size_t)bh * SS * DH;
    const float* Vb = g_v + (size_t)bh * SS * DH;

    // stage Q (x 0.125, fp16) into sp[warp], then load fragments to registers
    {
        #pragma unroll
        for (int i = 0; i < 8; i++) {
            const int idx = lane + i * 32;          // 0..255
            const int row = idx >> 4;               // 0..15
            const int cc  = (idx & 15) * 4;
            float4 t = *(const float4*)(Qb + (size_t)(qrow0 + row) * DH + cc);
            unsigned h0 = h2u(__floats2half2_rn(t.x * 0.125f, t.y * 0.125f));
            unsigned h1 = h2u(__floats2half2_rn(t.z * 0.125f, t.w * 0.125f));
            *(uint2*)&sp[warp][row][cc] = make_uint2(h0, h1);
        }
    }
    __syncwarp();
    unsigned qa[4][4];                              // 4 k16 steps over Dh=64
    #pragma unroll
    for (int ks = 0; ks < 4; ks++) {
        const int kk = ks * 16 + 2 * c4;
        qa[ks][0] = *(const unsigned*)&sp[warp][r4    ][kk    ];
        qa[ks][1] = *(const unsigned*)&sp[warp][r4 + 8][kk    ];
        qa[ks][2] = *(const unsigned*)&sp[warp][r4    ][kk + 8];
        qa[ks][3] = *(const unsigned*)&sp[warp][r4 + 8][kk + 8];
    }
    __syncwarp();

    float o[8][4];
    #pragma unroll
    for (int nt = 0; nt < 8; nt++)
        #pragma unroll
        for (int c = 0; c < 4; c++) o[nt][c] = 0.0f;
    float m0v = -INFINITY, m1v = -INFINITY;
    float l0 = 0.0f, l1 = 0.0f;

    for (int t0 = 0; t0 < SS; t0 += 64) {
        __syncthreads();
        // K: 64 rows x 64 cols, 8 float4 loads per thread
        #pragma unroll
        for (int i = 0; i < 8; i++) {
            const int idx = tid + i * 128;          // 0..1023
            const int row = idx >> 4;               // 0..63
            const int cc  = (idx & 15) * 4;
            float4 kt4 = *(const float4*)(Kb + (size_t)(t0 + row) * DH + cc);
            unsigned h0 = h2u(__floats2half2_rn(kt4.x, kt4.y));
            unsigned h1 = h2u(__floats2half2_rn(kt4.z, kt4.w));
            *(uint2*)&sk[row][cc] = make_uint2(h0, h1);
        }
        // V: 32 kv-pairs x 64 d's; thread -> (kvp = tid>>2, 16 d's)
        {
            const int kvp = tid >> 2;               // 0..31
            const int d0  = (tid & 3) * 16;         // 0,16,32,48
            const float* v0 = Vb + (size_t)(t0 + 2 * kvp) * DH + d0;
            const float* v1 = v0 + DH;
            #pragma unroll
            for (int half8 = 0; half8 < 2; half8++) {
                float4 a0 = *(const float4*)(v0 + 8 * half8);
                float4 a1 = *(const float4*)(v0 + 8 * half8 + 4);
                float4 b0 = *(const float4*)(v1 + 8 * half8);
                float4 b1 = *(const float4*)(v1 + 8 * half8 + 4);
                uint4 w0, w1;
                w0.x = h2u(__floats2half2_rn(a0.x, b0.x));
                w0.y = h2u(__floats2half2_rn(a0.y, b0.y));
                w0.z = h2u(__floats2half2_rn(a0.z, b0.z));
                w0.w = h2u(__floats2half2_rn(a0.w, b0.w));
                w1.x = h2u(__floats2half2_rn(a1.x, b1.x));
                w1.y = h2u(__floats2half2_rn(a1.y, b1.y));
                w1.z = h2u(__floats2half2_rn(a1.z, b1.z));
                w1.w = h2u(__floats2half2_rn(a1.w, b1.w));
                *(uint4*)&sv2[kvp][d0 + 8 * half8]     = w0;
                *(uint4*)&sv2[kvp][d0 + 8 * half8 + 4] = w1;
            }
        }
        __syncthreads();

        // S = Q @ K^T : 8 kv n-tiles x 4 k16 steps
        float s[8][4];
        #pragma unroll
        for (int nt = 0; nt < 8; nt++) {
            #pragma unroll
            for (int c = 0; c < 4; c++) s[nt][c] = 0.0f;
            #pragma unroll
            for (int ks = 0; ks < 4; ks++) {
                const int kk = ks * 16 + 2 * c4;
                unsigned bf[2];
                bf[0] = *(const unsigned*)&sk[nt * 8 + r4][kk    ];
                bf[1] = *(const unsigned*)&sk[nt * 8 + r4][kk + 8];
                mma_f16(s[nt], qa[ks], bf);
            }
        }

        // online softmax (fp32)
        float tm0 = -INFINITY, tm1 = -INFINITY;
        #pragma unroll
        for (int nt = 0; nt < 8; nt++) {
            tm0 = fmaxf(tm0, fmaxf(s[nt][0], s[nt][1]));
            tm1 = fmaxf(tm1, fmaxf(s[nt][2], s[nt][3]));
        }
        tm0 = fmaxf(tm0, __shfl_xor_sync(0xffffffffu, tm0, 1));
        tm0 = fmaxf(tm0, __shfl_xor_sync(0xffffffffu, tm0, 2));
        tm1 = fmaxf(tm1, __shfl_xor_sync(0xffffffffu, tm1, 1));
        tm1 = fmaxf(tm1, __shfl_xor_sync(0xffffffffu, tm1, 2));

        const float mn0 = fmaxf(m0v, tm0);
        const float mn1 = fmaxf(m1v, tm1);
        const float sc0 = __expf(m0v - mn0);
        const float sc1 = __expf(m1v - mn1);
        m0v = mn0; m1v = mn1;

        float ps0 = 0.0f, ps1 = 0.0f;
        #pragma unroll
        for (int nt = 0; nt < 8; nt++) {
            s[nt][0] = __expf(s[nt][0] - mn0);
            s[nt][1] = __expf(s[nt][1] - mn0);
            s[nt][2] = __expf(s[nt][2] - mn1);
            s[nt][3] = __expf(s[nt][3] - mn1);
            ps0 += s[nt][0] + s[nt][1];
            ps1 += s[nt][2] + s[nt][3];
        }
        ps0 += __shfl_xor_sync(0xffffffffu, ps0, 1);
        ps0 += __shfl_xor_sync(0xffffffffu, ps0, 2);
        ps1 += __shfl_xor_sync(0xffffffffu, ps1, 1);
        ps1 += __shfl_xor_sync(0xffffffffu, ps1, 2);
        l0 = l0 * sc0 + ps0;
        l1 = l1 * sc1 + ps1;

        #pragma unroll
        for (int nt = 0; nt < 8; nt++) {
            o[nt][0] *= sc0; o[nt][1] *= sc0;
            o[nt][2] *= sc1; o[nt][3] *= sc1;
        }

        // P (fp16) -> warp-private smem (16 x 64); reload as A fragments
        #pragma unroll
        for (int nt = 0; nt < 8; nt++) {
            const int pc = nt * 8 + 2 * c4;
            *(unsigned*)&sp[warp][r4    ][pc] = h2u(__floats2half2_rn(s[nt][0], s[nt][1]));
            *(unsigned*)&sp[warp][r4 + 8][pc] = h2u(__floats2half2_rn(s[nt][2], s[nt][3]));
        }
        __syncwarp();

        unsigned pa[4][4];                          // 4 k16 steps over kv=64
        #pragma unroll
        for (int ks = 0; ks < 4; ks++) {
            const int kk = ks * 16 + 2 * c4;
            pa[ks][0] = *(const unsigned*)&sp[warp][r4    ][kk    ];
            pa[ks][1] = *(const unsigned*)&sp[warp][r4 + 8][kk    ];
            pa[ks][2] = *(const unsigned*)&sp[warp][r4    ][kk + 8];
            pa[ks][3] = *(const unsigned*)&sp[warp][r4 + 8][kk + 8];
        }

        // O += P @ V : 8 dh n-tiles x 4 k16 steps
        #pragma unroll
        for (int nt = 0; nt < 8; nt++) {
            #pragma unroll
            for (int ks = 0; ks < 4; ks++) {
                unsigned bf[2];
                bf[0] = sv2[ks * 8 + c4    ][nt * 8 + r4];
                bf[1] = sv2[ks * 8 + c4 + 4][nt * 8 + r4];
                mma_f16(o[nt], pa[ks], bf);
            }
        }
        __syncwarp();
    }

    // epilogue: normalize and store
    const float inv0 = 1.0f / l0;
    const float inv1 = 1.0f / l1;
    const int rA = qrow0 + r4;
    const int rB = rA + 8;
    float* oA = out + ((size_t)(b * SS + rA)) * DD + h * DH;
    float* oB = out + ((size_t)(b * SS + rB)) * DD + h * DH;
    #pragma unroll
    for (int nt = 0; nt < 8; nt++) {
        const int d = nt * 8 + 2 * c4;
        *(float2*)(oA + d) = make_float2(o[nt][0] * inv0, o[nt][1] * inv0);
        *(float2*)(oB + d) = make_float2(o[nt][2] * inv1, o[nt][3] * inv1);
    }
}

extern "C" void kernel_launch(void* const* d_in, const int* in_sizes, int n_in,
                              void* d_out, int out_size)
{
    const float* x  = (const float*)d_in[0];
    const float* Wq = (const float*)d_in[1];
    const float* bq = (const float*)d_in[2];
    const float* Wk = (const float*)d_in[3];
    const float* bk = (const float*)d_in[4];
    const float* Wv = (const float*)d_in[5];
    const float* bv = (const float*)d_in[6];
    float* out = (float*)d_out;

    __half* gxh; cudaGetSymbolAddress((void**)&gxh, g_xh);
    __half* gwh; cudaGetSymbolAddress((void**)&gwh, g_wh);

    to_half<<<(BB * SS * DD / 8 + 255) / 256, 256>>>(gxh, x, BB * SS * DD / 8);
    to_half<<<(DD * DD / 8 + 255) / 256, 256>>>(gwh,               Wq, DD * DD / 8);
    to_half<<<(DD * DD / 8 + 255) / 256, 256>>>(gwh + DD * DD,     Wk, DD * DD / 8);
    to_half<<<(DD * DD / 8 + 255) / 256, 256>>>(gwh + 2 * DD * DD, Wv, DD * DD / 8);

    dim3 gg(DD / 128, (BB * SS) / 128);   // (8, 128)
    qkv_gemm<<<gg, 256>>>(bq, 0);
    qkv_gemm<<<gg, 256>>>(bk, 1);
    qkv_gemm<<<gg, 256>>>(bv, 2);

    dim3 ga(SS / 64, BB * HH);            // (16, 256)
    attn_kernel<<<ga, 128>>>(out);
}